// round 2
// baseline (speedup 1.0000x reference)
#include <cuda_runtime.h>

// ---------------------------------------------------------------------------
// BBoxHead: logits/probs/deltas = head( BNReLU( BNReLU( X@W1 )@W2 ) )
//   X [2000, 7*7*256=12544], W1 [12544,1024], W2 [1024,1024]
//   W_logits [1024,81], W_delta [1024,324]
//   out = [logits (2000*81) | probs (2000*81) | deltas (2000*324)] fp32
// ---------------------------------------------------------------------------

#define N_ROI  2000
#define K1     12544
#define HID    1024
#define NCLS   81
#define NDEL   324
#define BN_EPS 1e-3f

// Scratch (no allocations allowed)
__device__ float g_x1[N_ROI * HID];
__device__ float g_x2[N_ROI * HID];
__device__ float g_scale[HID];
__device__ float g_shift[HID];

// ---------------------------------------------------------------------------
// Fast SGEMM: C[M,N] = A[M,K] @ B[K,N] + bias[N]
// Requires: N % 128 == 0, K % 16 == 0 (K % 4 == 0 for float4 A loads).
// Guards M only. 128x128x16 block tile, 256 threads, 8x8 per-thread microtile.
// ---------------------------------------------------------------------------
__global__ __launch_bounds__(256)
void sgemm_bias_fast(const float* __restrict__ A, const float* __restrict__ B,
                     const float* __restrict__ bias, float* __restrict__ C,
                     int M, int N, int K) {
    constexpr int BM = 128, BN = 128, BK = 16;
    __shared__ float As[BK][BM];
    __shared__ float Bs[BK][BN];

    const int tid  = threadIdx.x;
    const int row0 = blockIdx.y * BM;
    const int col0 = blockIdx.x * BN;
    const int tm   = tid / 16;   // 0..15
    const int tn   = tid % 16;   // 0..15

    float acc[8][8];
#pragma unroll
    for (int i = 0; i < 8; i++)
#pragma unroll
        for (int j = 0; j < 8; j++) acc[i][j] = 0.0f;

    for (int k0 = 0; k0 < K; k0 += BK) {
        // A tile: BM x BK, float4 along K, transposed into As[k][m]
#pragma unroll
        for (int e = tid; e < BM * BK / 4; e += 256) {
            int r  = e / (BK / 4);         // 0..127
            int kc = (e % (BK / 4)) * 4;   // 0,4,8,12
            float4 v = make_float4(0.f, 0.f, 0.f, 0.f);
            int gr = row0 + r;
            if (gr < M) v = *(const float4*)&A[(size_t)gr * K + k0 + kc];
            As[kc + 0][r] = v.x;
            As[kc + 1][r] = v.y;
            As[kc + 2][r] = v.z;
            As[kc + 3][r] = v.w;
        }
        // B tile: BK x BN, float4 along N
#pragma unroll
        for (int e = tid; e < BK * BN / 4; e += 256) {
            int r = e / (BN / 4);          // 0..15
            int c = (e % (BN / 4)) * 4;
            float4 v = *(const float4*)&B[(size_t)(k0 + r) * N + col0 + c];
            *(float4*)&Bs[r][c] = v;
        }
        __syncthreads();

#pragma unroll
        for (int k = 0; k < BK; k++) {
            float a[8], b[8];
            *(float4*)&a[0] = *(const float4*)&As[k][tm * 8];
            *(float4*)&a[4] = *(const float4*)&As[k][tm * 8 + 4];
            *(float4*)&b[0] = *(const float4*)&Bs[k][tn * 8];
            *(float4*)&b[4] = *(const float4*)&Bs[k][tn * 8 + 4];
#pragma unroll
            for (int i = 0; i < 8; i++)
#pragma unroll
                for (int j = 0; j < 8; j++)
                    acc[i][j] = fmaf(a[i], b[j], acc[i][j]);
        }
        __syncthreads();
    }

#pragma unroll
    for (int i = 0; i < 8; i++) {
        int gr = row0 + tm * 8 + i;
        if (gr < M) {
#pragma unroll
            for (int j = 0; j < 8; j += 4) {
                int gc = col0 + tn * 8 + j;
                float4 v;
                v.x = acc[i][j + 0] + bias[gc + 0];
                v.y = acc[i][j + 1] + bias[gc + 1];
                v.z = acc[i][j + 2] + bias[gc + 2];
                v.w = acc[i][j + 3] + bias[gc + 3];
                *(float4*)&C[(size_t)gr * N + gc] = v;
            }
        }
    }
}

// ---------------------------------------------------------------------------
// BatchNorm (training stats over rows) — compute per-column scale/shift.
// grid: N/32 blocks, block (32,8). Coalesced row-major reads.
// ---------------------------------------------------------------------------
__global__ void bn_stats_kernel(const float* __restrict__ x,
                                const float* __restrict__ gamma,
                                const float* __restrict__ beta,
                                float* __restrict__ scale,
                                float* __restrict__ shift,
                                int M, int N) {
    int col = blockIdx.x * 32 + threadIdx.x;
    float s = 0.f, sq = 0.f;
    for (int r = threadIdx.y; r < M; r += blockDim.y) {
        float v = x[(size_t)r * N + col];
        s += v;
        sq += v * v;
    }
    __shared__ float ss[8][32];
    __shared__ float sg[8][32];
    ss[threadIdx.y][threadIdx.x] = s;
    sg[threadIdx.y][threadIdx.x] = sq;
    __syncthreads();
    if (threadIdx.y == 0) {
#pragma unroll
        for (int i = 1; i < 8; i++) {
            s  += ss[i][threadIdx.x];
            sq += sg[i][threadIdx.x];
        }
        float mean = s / (float)M;
        float var  = sq / (float)M - mean * mean;
        float sc   = gamma[col] * rsqrtf(var + BN_EPS);
        scale[col] = sc;
        shift[col] = beta[col] - mean * sc;
    }
}

// y = relu(x*scale + shift), in place. N must be power of two (1024).
__global__ void bn_relu_kernel(float* __restrict__ x,
                               const float* __restrict__ scale,
                               const float* __restrict__ shift,
                               int total, int N) {
    int i = blockIdx.x * blockDim.x + threadIdx.x;
    if (i < total) {
        int c = i & (N - 1);
        x[i] = fmaxf(0.f, fmaf(x[i], scale[c], shift[c]));
    }
}

// ---------------------------------------------------------------------------
// Heads: logits (N=81) + deltas (N=324) from X [M,1024] in one launch.
// blockIdx.x == 0 -> logits; 1..3 -> delta column-blocks. Guarded everywhere.
// ---------------------------------------------------------------------------
__global__ __launch_bounds__(256)
void heads_gemm_kernel(const float* __restrict__ X,
                       const float* __restrict__ Wl, const float* __restrict__ bl,
                       const float* __restrict__ Wd, const float* __restrict__ bd,
                       float* __restrict__ out_logits,
                       float* __restrict__ out_deltas,
                       int M) {
    constexpr int BM = 128, BN = 128, BK = 16, K = HID;
    __shared__ float As[BK][BM];
    __shared__ float Bs[BK][BN];

    const float* B;
    const float* bias;
    float* C;
    int N, col0;
    if (blockIdx.x == 0) { B = Wl; bias = bl; C = out_logits; N = NCLS; col0 = 0; }
    else { B = Wd; bias = bd; C = out_deltas; N = NDEL; col0 = (blockIdx.x - 1) * BN; }

    const int tid  = threadIdx.x;
    const int row0 = blockIdx.y * BM;
    const int tm   = tid / 16;
    const int tn   = tid % 16;

    float acc[8][8];
#pragma unroll
    for (int i = 0; i < 8; i++)
#pragma unroll
        for (int j = 0; j < 8; j++) acc[i][j] = 0.0f;

    for (int k0 = 0; k0 < K; k0 += BK) {
        // A tile (float4, M guard)
#pragma unroll
        for (int e = tid; e < BM * BK / 4; e += 256) {
            int r  = e / (BK / 4);
            int kc = (e % (BK / 4)) * 4;
            float4 v = make_float4(0.f, 0.f, 0.f, 0.f);
            int gr = row0 + r;
            if (gr < M) v = *(const float4*)&X[(size_t)gr * K + k0 + kc];
            As[kc + 0][r] = v.x;
            As[kc + 1][r] = v.y;
            As[kc + 2][r] = v.z;
            As[kc + 3][r] = v.w;
        }
        // B tile (scalar, N guard)
#pragma unroll
        for (int e = tid; e < BK * BN; e += 256) {
            int r = e / BN;
            int c = e % BN;
            int gc = col0 + c;
            Bs[r][c] = (gc < N) ? B[(size_t)(k0 + r) * N + gc] : 0.f;
        }
        __syncthreads();

#pragma unroll
        for (int k = 0; k < BK; k++) {
            float a[8], b[8];
            *(float4*)&a[0] = *(const float4*)&As[k][tm * 8];
            *(float4*)&a[4] = *(const float4*)&As[k][tm * 8 + 4];
            *(float4*)&b[0] = *(const float4*)&Bs[k][tn * 8];
            *(float4*)&b[4] = *(const float4*)&Bs[k][tn * 8 + 4];
#pragma unroll
            for (int i = 0; i < 8; i++)
#pragma unroll
                for (int j = 0; j < 8; j++)
                    acc[i][j] = fmaf(a[i], b[j], acc[i][j]);
        }
        __syncthreads();
    }

#pragma unroll
    for (int i = 0; i < 8; i++) {
        int gr = row0 + tm * 8 + i;
        if (gr >= M) continue;
#pragma unroll
        for (int j = 0; j < 8; j++) {
            int gc = col0 + tn * 8 + j;
            if (gc < N) C[(size_t)gr * N + gc] = acc[i][j] + bias[gc];
        }
    }
}

// Softmax over 81 classes, one warp per row.
__global__ void softmax_kernel(const float* __restrict__ logits,
                               float* __restrict__ probs, int M, int N) {
    int row  = blockIdx.x * (blockDim.x / 32) + threadIdx.x / 32;
    int lane = threadIdx.x & 31;
    if (row >= M) return;
    const float* lr = logits + (size_t)row * N;
    float v[3];
    float mx = -1e30f;
#pragma unroll
    for (int j = 0; j < 3; j++) {
        int c = lane + j * 32;
        v[j] = (c < N) ? lr[c] : -1e30f;
        mx = fmaxf(mx, v[j]);
    }
#pragma unroll
    for (int o = 16; o; o >>= 1) mx = fmaxf(mx, __shfl_xor_sync(0xFFFFFFFFu, mx, o));
    float s = 0.f;
#pragma unroll
    for (int j = 0; j < 3; j++) {
        int c = lane + j * 32;
        v[j] = (c < N) ? expf(v[j] - mx) : 0.f;
        s += v[j];
    }
#pragma unroll
    for (int o = 16; o; o >>= 1) s += __shfl_xor_sync(0xFFFFFFFFu, s, o);
    float inv = 1.0f / s;
#pragma unroll
    for (int j = 0; j < 3; j++) {
        int c = lane + j * 32;
        if (c < N) probs[(size_t)row * N + c] = v[j] * inv;
    }
}

// ---------------------------------------------------------------------------
extern "C" void kernel_launch(void* const* d_in, const int* in_sizes, int n_in,
                              void* d_out, int out_size) {
    const float* pooled   = (const float*)d_in[0];   // [2000, 7,7,256]
    const float* w1       = (const float*)d_in[1];   // [12544, 1024]
    const float* b1       = (const float*)d_in[2];
    const float* gamma1   = (const float*)d_in[3];
    const float* beta1    = (const float*)d_in[4];
    const float* w2       = (const float*)d_in[5];   // [1024, 1024]
    const float* b2       = (const float*)d_in[6];
    const float* gamma2   = (const float*)d_in[7];
    const float* beta2    = (const float*)d_in[8];
    const float* w_logits = (const float*)d_in[9];   // [1024, 81]
    const float* b_logits = (const float*)d_in[10];
    const float* w_delta  = (const float*)d_in[11];  // [1024, 324]
    const float* b_delta  = (const float*)d_in[12];

    float* out        = (float*)d_out;
    float* out_logits = out;                      // 2000*81
    float* out_probs  = out + N_ROI * NCLS;       // 2000*81
    float* out_deltas = out + 2 * N_ROI * NCLS;   // 2000*324

    float *x1, *x2, *scale, *shift;
    cudaGetSymbolAddress((void**)&x1, g_x1);
    cudaGetSymbolAddress((void**)&x2, g_x2);
    cudaGetSymbolAddress((void**)&scale, g_scale);
    cudaGetSymbolAddress((void**)&shift, g_shift);

    const int total = N_ROI * HID;
    dim3 gemm_grid(HID / 128, (N_ROI + 127) / 128);   // (8, 16)
    dim3 bn_block(32, 8);

    // x1 = X @ W1 + b1
    sgemm_bias_fast<<<gemm_grid, 256>>>(pooled, w1, b1, x1, N_ROI, HID, K1);
    // BN1 + ReLU (training stats)
    bn_stats_kernel<<<HID / 32, bn_block>>>(x1, gamma1, beta1, scale, shift, N_ROI, HID);
    bn_relu_kernel<<<(total + 255) / 256, 256>>>(x1, scale, shift, total, HID);
    // x2 = x1 @ W2 + b2
    sgemm_bias_fast<<<gemm_grid, 256>>>(x1, w2, b2, x2, N_ROI, HID, HID);
    // BN2 + ReLU
    bn_stats_kernel<<<HID / 32, bn_block>>>(x2, gamma2, beta2, scale, shift, N_ROI, HID);
    bn_relu_kernel<<<(total + 255) / 256, 256>>>(x2, scale, shift, total, HID);
    // logits + deltas
    dim3 heads_grid(4, (N_ROI + 127) / 128);          // (4, 16)
    heads_gemm_kernel<<<heads_grid, 256>>>(x2, w_logits, b_logits, w_delta, b_delta,
                                           out_logits, out_deltas, N_ROI);
    // probs = softmax(logits)
    softmax_kernel<<<(N_ROI + 7) / 8, 256>>>(out_logits, out_probs, N_ROI, NCLS);
}

// round 4
// speedup vs baseline: 1.9208x; 1.9208x over previous
#include <cuda_runtime.h>
#include <mma.h>
#include <cstdint>

using namespace nvcuda;

// ---------------------------------------------------------------------------
// BBoxHead via legacy tensor-core tf32 WMMA GEMMs (compute_103-safe).
//   GEMM1: X[2000,12544] @ W1 -> x1[2000,1024] (+b1), BN+ReLU(+rna)
//   GEMM2: x1 @ W2 -> x2 (+b2), BN+ReLU(+rna)
//   HEADS: x2 @ [Wl|Wd] (N padded to 512) -> logits/deltas, softmax
// B operands pre-transposed to [N,K] K-major with cvt.rna.tf32.
// ---------------------------------------------------------------------------

#define N_ROI  2000
#define K1     12544
#define HID    1024
#define NCLS   81
#define NDEL   324
#define NHEAD  405
#define NHPAD  512
#define BN_EPS 1e-3f

__device__ float g_At  [N_ROI * K1];
__device__ float g_W1t [HID * K1];
__device__ float g_W2t [HID * HID];
__device__ float g_Wht [NHPAD * HID];
__device__ float g_bh  [NHPAD];
__device__ float g_x1  [2048 * HID];
__device__ float g_x2  [2048 * HID];
__device__ float g_heads[N_ROI * NHPAD];
__device__ float g_scale[HID];
__device__ float g_shift[HID];

// ---------------------------------------------------------------------------
__device__ __forceinline__ uint32_t smem_u32(const void* p) {
    uint32_t a;
    asm("{ .reg .u64 t; cvta.to.shared.u64 t, %1; cvt.u32.u64 %0, t; }" : "=r"(a) : "l"(p));
    return a;
}
__device__ __forceinline__ float rna_tf32(float x) {
    uint32_t r;
    asm("cvt.rna.tf32.f32 %0, %1;" : "=r"(r) : "f"(x));
    return __uint_as_float(r);
}
__device__ __forceinline__ void cp_async16(uint32_t saddr, const void* g, bool valid) {
    int sz = valid ? 16 : 0;
    asm volatile("cp.async.cg.shared.global [%0], [%1], 16, %2;"
                 :: "r"(saddr), "l"(g), "r"(sz) : "memory");
}
__device__ __forceinline__ void cp_commit() {
    asm volatile("cp.async.commit_group;" ::: "memory");
}
template<int N> __device__ __forceinline__ void cp_wait() {
    asm volatile("cp.async.wait_group %0;" :: "n"(N) : "memory");
}

// ---------------------------------------------------------------------------
// tf32 WMMA GEMM: C[M, ldC] = A[M,K] @ Bt[N,K]^T + bias
// 128x128 CTA tile, BK=32, 3-stage cp.async pipeline, 256 threads (8 warps),
// warp tile 32x64 (2x4 wmma m16n16k8 frags).
// grid = (ldC/128, ceil(M/128)); Bt rows must cover grid (pre-padded).
// ---------------------------------------------------------------------------
#define LDT        36                    // 32 + 4 pad (floats); row = 144 B (16-aligned)
#define HALF_STAGE (128 * LDT * 4)       // 18432 B (one matrix tile)
#define STAGE_B    (2 * HALF_STAGE)      // A + B per stage
#define NSTAGE     3
#define SMEM_TOT   (NSTAGE * STAGE_B)    // 110592 B
#define LDE        132                   // epilogue smem stride

__device__ __forceinline__ void fill_tile(uint32_t sbase, const float* __restrict__ gb,
                                          int ldg, int row0, int maxrow, int k0, int tid) {
#pragma unroll
    for (int r = 0; r < 4; r++) {
        int id  = tid + r * 256;
        int row = id >> 3;
        int c16 = id & 7;
        uint32_t sa = sbase + row * (LDT * 4) + c16 * 16;
        const float* g = gb + (size_t)(row0 + row) * ldg + k0 + c16 * 4;
        cp_async16(sa, g, (row0 + row) < maxrow);
    }
}

__global__ __launch_bounds__(256)
void gemm_tf32(const float* __restrict__ A, const float* __restrict__ Bt,
               const float* __restrict__ bias, float* __restrict__ C,
               int M, int K, int ldC) {
    extern __shared__ float smem[];
    const uint32_t sb = smem_u32(smem);
    const int tid = threadIdx.x;
    const int wid = tid >> 5;
    const int row0 = blockIdx.y * 128;
    const int col0 = blockIdx.x * 128;
    const int warp_m = wid & 3;     // 0..3 -> 32-row strip
    const int warp_n = wid >> 2;    // 0..1 -> 64-col strip
    const int NK = K / 32;

    wmma::fragment<wmma::accumulator, 16, 16, 8, float> fc[2][4];
#pragma unroll
    for (int i = 0; i < 2; i++)
#pragma unroll
        for (int j = 0; j < 4; j++) wmma::fill_fragment(fc[i][j], 0.0f);

    // prologue: fill stages 0,1
    fill_tile(sb + 0 * STAGE_B,              A,  K, row0, M,       0,  tid);
    fill_tile(sb + 0 * STAGE_B + HALF_STAGE, Bt, K, col0, 1 << 30, 0,  tid);
    cp_commit();
    if (NK > 1) {
        fill_tile(sb + 1 * STAGE_B,              A,  K, row0, M,       32, tid);
        fill_tile(sb + 1 * STAGE_B + HALF_STAGE, Bt, K, col0, 1 << 30, 32, tid);
    }
    cp_commit();

    int s = 0;
    for (int i = 0; i < NK; i++) {
        cp_wait<1>();
        __syncthreads();

        const float* As = smem + s * (STAGE_B / 4);
        const float* Bs = As + (HALF_STAGE / 4);
        const float* Aw = As + (warp_m * 32) * LDT;
        const float* Bw = Bs + (warp_n * 64) * LDT;

#pragma unroll
        for (int ks = 0; ks < 4; ks++) {
            wmma::fragment<wmma::matrix_a, 16, 16, 8, wmma::precision::tf32, wmma::row_major> fa[2];
            wmma::fragment<wmma::matrix_b, 16, 16, 8, wmma::precision::tf32, wmma::col_major> fb[4];
#pragma unroll
            for (int ii = 0; ii < 2; ii++)
                wmma::load_matrix_sync(fa[ii], Aw + ii * 16 * LDT + ks * 8, LDT);
#pragma unroll
            for (int jj = 0; jj < 4; jj++)
                wmma::load_matrix_sync(fb[jj], Bw + jj * 16 * LDT + ks * 8, LDT);
#pragma unroll
            for (int ii = 0; ii < 2; ii++)
#pragma unroll
                for (int jj = 0; jj < 4; jj++)
                    wmma::mma_sync(fc[ii][jj], fa[ii], fb[jj], fc[ii][jj]);
        }

        if (i + 2 < NK) {
            int sn = (s + 2 >= NSTAGE) ? s + 2 - NSTAGE : s + 2;
            fill_tile(sb + sn * STAGE_B,              A,  K, row0, M,       (i + 2) * 32, tid);
            fill_tile(sb + sn * STAGE_B + HALF_STAGE, Bt, K, col0, 1 << 30, (i + 2) * 32, tid);
        }
        cp_commit();
        s = (s + 1 == NSTAGE) ? 0 : s + 1;
    }

    // epilogue: frags -> smem -> global (+bias), M-guarded, float4 stores
    cp_wait<0>();
    __syncthreads();
    float* esm = smem;   // 128 x LDE floats = 67584 B < SMEM_TOT
#pragma unroll
    for (int ii = 0; ii < 2; ii++)
#pragma unroll
        for (int jj = 0; jj < 4; jj++)
            wmma::store_matrix_sync(esm + (warp_m * 32 + ii * 16) * LDE + warp_n * 64 + jj * 16,
                                    fc[ii][jj], LDE, wmma::mem_row_major);
    __syncthreads();
#pragma unroll 4
    for (int e = tid; e < 128 * 32; e += 256) {
        int r  = e >> 5;
        int c4 = (e & 31) * 4;
        int gr = row0 + r;
        if (gr < M) {
            const float* sp = esm + r * LDE + c4;
            float4 v;
            v.x = sp[0] + bias[col0 + c4 + 0];
            v.y = sp[1] + bias[col0 + c4 + 1];
            v.z = sp[2] + bias[col0 + c4 + 2];
            v.w = sp[3] + bias[col0 + c4 + 3];
            *(float4*)&C[(size_t)gr * ldC + col0 + c4] = v;
        }
    }
}

// ---------------------------------------------------------------------------
// Prep kernels
// ---------------------------------------------------------------------------
__global__ void cvt_rna_copy(const float* __restrict__ in, float* __restrict__ out, int n4) {
    int i = blockIdx.x * blockDim.x + threadIdx.x;
    if (i < n4) {
        float4 v = ((const float4*)in)[i];
        v.x = rna_tf32(v.x); v.y = rna_tf32(v.y);
        v.z = rna_tf32(v.z); v.w = rna_tf32(v.w);
        ((float4*)out)[i] = v;
    }
}

__global__ void transpose_rna(const float* __restrict__ in, float* __restrict__ out,
                              int K, int Nc, int ldout, int row_off) {
    __shared__ float t[32][33];
    int k0 = blockIdx.x * 32, n0 = blockIdx.y * 32;
    int x = threadIdx.x, y = threadIdx.y;
#pragma unroll
    for (int yy = y; yy < 32; yy += 8) {
        int k = k0 + yy, n = n0 + x;
        t[yy][x] = (k < K && n < Nc) ? in[(size_t)k * Nc + n] : 0.f;
    }
    __syncthreads();
#pragma unroll
    for (int yy = y; yy < 32; yy += 8) {
        int n = n0 + yy, k = k0 + x;
        if (n < Nc && k < K)
            out[(size_t)(row_off + n) * ldout + k] = rna_tf32(t[x][yy]);
    }
}

__global__ void head_pad_init(const float* __restrict__ bl, const float* __restrict__ bd,
                              float* __restrict__ bh, float* __restrict__ wht) {
    int i = blockIdx.x * blockDim.x + threadIdx.x;
    if (i < NHPAD)
        bh[i] = (i < NCLS) ? bl[i] : (i < NHEAD ? bd[i - NCLS] : 0.f);
    for (int j = i; j < (NHPAD - NHEAD) * HID; j += gridDim.x * blockDim.x)
        wht[(size_t)NHEAD * HID + j] = 0.f;
}

// ---------------------------------------------------------------------------
// BN / activation / heads epilogue
// ---------------------------------------------------------------------------
__global__ void bn_stats_kernel(const float* __restrict__ x,
                                const float* __restrict__ gamma,
                                const float* __restrict__ beta,
                                float* __restrict__ scale, float* __restrict__ shift,
                                int M, int N) {
    int col = blockIdx.x * 32 + threadIdx.x;
    float s = 0.f, sq = 0.f;
    for (int r = threadIdx.y; r < M; r += blockDim.y) {
        float v = x[(size_t)r * N + col];
        s += v; sq += v * v;
    }
    __shared__ float ss[8][32], sg[8][32];
    ss[threadIdx.y][threadIdx.x] = s;
    sg[threadIdx.y][threadIdx.x] = sq;
    __syncthreads();
    if (threadIdx.y == 0) {
#pragma unroll
        for (int i = 1; i < 8; i++) { s += ss[i][threadIdx.x]; sq += sg[i][threadIdx.x]; }
        float mean = s / (float)M;
        float var  = sq / (float)M - mean * mean;
        float sc   = gamma[col] * rsqrtf(var + BN_EPS);
        scale[col] = sc;
        shift[col] = beta[col] - mean * sc;
    }
}

__global__ void bn_relu_rna_kernel(float* __restrict__ x, const float* __restrict__ scale,
                                   const float* __restrict__ shift, int total, int N) {
    int i = blockIdx.x * blockDim.x + threadIdx.x;
    if (i < total) {
        int c = i & (N - 1);
        x[i] = rna_tf32(fmaxf(0.f, fmaf(x[i], scale[c], shift[c])));
    }
}

__global__ void scatter_heads(const float* __restrict__ heads,
                              float* __restrict__ out_logits,
                              float* __restrict__ out_deltas) {
    int i = blockIdx.x * blockDim.x + threadIdx.x;
    if (i < N_ROI * NHEAD) {
        int r = i / NHEAD, c = i % NHEAD;
        float v = heads[(size_t)r * NHPAD + c];
        if (c < NCLS) out_logits[(size_t)r * NCLS + c] = v;
        else          out_deltas[(size_t)r * NDEL + (c - NCLS)] = v;
    }
}

__global__ void softmax_kernel(const float* __restrict__ logits,
                               float* __restrict__ probs, int M, int N) {
    int row  = blockIdx.x * (blockDim.x / 32) + threadIdx.x / 32;
    int lane = threadIdx.x & 31;
    if (row >= M) return;
    const float* lr = logits + (size_t)row * N;
    float v[3], mx = -1e30f;
#pragma unroll
    for (int j = 0; j < 3; j++) {
        int c = lane + j * 32;
        v[j] = (c < N) ? lr[c] : -1e30f;
        mx = fmaxf(mx, v[j]);
    }
#pragma unroll
    for (int o = 16; o; o >>= 1) mx = fmaxf(mx, __shfl_xor_sync(0xFFFFFFFFu, mx, o));
    float s = 0.f;
#pragma unroll
    for (int j = 0; j < 3; j++) {
        int c = lane + j * 32;
        v[j] = (c < N) ? expf(v[j] - mx) : 0.f;
        s += v[j];
    }
#pragma unroll
    for (int o = 16; o; o >>= 1) s += __shfl_xor_sync(0xFFFFFFFFu, s, o);
    float inv = 1.0f / s;
#pragma unroll
    for (int j = 0; j < 3; j++) {
        int c = lane + j * 32;
        if (c < N) probs[(size_t)row * N + c] = v[j] * inv;
    }
}

// ---------------------------------------------------------------------------
extern "C" void kernel_launch(void* const* d_in, const int* in_sizes, int n_in,
                              void* d_out, int out_size) {
    const float* pooled   = (const float*)d_in[0];
    const float* w1       = (const float*)d_in[1];
    const float* b1       = (const float*)d_in[2];
    const float* gamma1   = (const float*)d_in[3];
    const float* beta1    = (const float*)d_in[4];
    const float* w2       = (const float*)d_in[5];
    const float* b2       = (const float*)d_in[6];
    const float* gamma2   = (const float*)d_in[7];
    const float* beta2    = (const float*)d_in[8];
    const float* w_logits = (const float*)d_in[9];
    const float* b_logits = (const float*)d_in[10];
    const float* w_delta  = (const float*)d_in[11];
    const float* b_delta  = (const float*)d_in[12];

    float* out        = (float*)d_out;
    float* out_logits = out;
    float* out_probs  = out + N_ROI * NCLS;
    float* out_deltas = out + 2 * N_ROI * NCLS;

    float *At, *W1t, *W2t, *Wht, *bh, *x1, *x2, *heads, *scale, *shift;
    cudaGetSymbolAddress((void**)&At,    g_At);
    cudaGetSymbolAddress((void**)&W1t,   g_W1t);
    cudaGetSymbolAddress((void**)&W2t,   g_W2t);
    cudaGetSymbolAddress((void**)&Wht,   g_Wht);
    cudaGetSymbolAddress((void**)&bh,    g_bh);
    cudaGetSymbolAddress((void**)&x1,    g_x1);
    cudaGetSymbolAddress((void**)&x2,    g_x2);
    cudaGetSymbolAddress((void**)&heads, g_heads);
    cudaGetSymbolAddress((void**)&scale, g_scale);
    cudaGetSymbolAddress((void**)&shift, g_shift);

    cudaFuncSetAttribute(gemm_tf32, cudaFuncAttributeMaxDynamicSharedMemorySize, SMEM_TOT);

    // prep: rna-convert A, transpose+rna weights, pad heads
    {
        int n4 = N_ROI * K1 / 4;
        cvt_rna_copy<<<(n4 + 255) / 256, 256>>>(pooled, At, n4);
        dim3 tb(32, 8);
        transpose_rna<<<dim3(K1 / 32, HID / 32), tb>>>(w1, W1t, K1, HID, K1, 0);
        transpose_rna<<<dim3(HID / 32, HID / 32), tb>>>(w2, W2t, HID, HID, HID, 0);
        transpose_rna<<<dim3(HID / 32, (NCLS + 31) / 32), tb>>>(w_logits, Wht, HID, NCLS, HID, 0);
        transpose_rna<<<dim3(HID / 32, (NDEL + 31) / 32), tb>>>(w_delta,  Wht, HID, NDEL, HID, NCLS);
        head_pad_init<<<64, 256>>>(b_logits, b_delta, bh, Wht);
    }

    const int total = N_ROI * HID;
    dim3 bn_block(32, 8);
    dim3 g1(HID / 128, 16);

    gemm_tf32<<<g1, 256, SMEM_TOT>>>(At, W1t, b1, x1, N_ROI, K1, HID);
    bn_stats_kernel<<<HID / 32, bn_block>>>(x1, gamma1, beta1, scale, shift, N_ROI, HID);
    bn_relu_rna_kernel<<<(total + 255) / 256, 256>>>(x1, scale, shift, total, HID);

    gemm_tf32<<<g1, 256, SMEM_TOT>>>(x1, W2t, b2, x2, N_ROI, HID, HID);
    bn_stats_kernel<<<HID / 32, bn_block>>>(x2, gamma2, beta2, scale, shift, N_ROI, HID);
    bn_relu_rna_kernel<<<(total + 255) / 256, 256>>>(x2, scale, shift, total, HID);

    dim3 gh(NHPAD / 128, 16);
    gemm_tf32<<<gh, 256, SMEM_TOT>>>(x2, Wht, bh, heads, N_ROI, HID, NHPAD);
    scatter_heads<<<(N_ROI * NHEAD + 255) / 256, 256>>>(heads, out_logits, out_deltas);
    softmax_kernel<<<(N_ROI + 7) / 8, 256>>>(out_logits, out_probs, N_ROI, NCLS);
}